// round 4
// baseline (speedup 1.0000x reference)
#include <cuda_runtime.h>
#include <cuda_bf16.h>

#ifndef S_SCALE
#define S_SCALE 64.0f
#endif
#ifndef MARGIN
#define MARGIN 0.35f
#endif

#define MAX_B 4096
__device__ float g_rowL[MAX_B];

// One CTA per row: sum exp(S*x) over the row, then compute per-row loss term.
__global__ __launch_bounds__(512) void row_loss_kernel(
    const float* __restrict__ x,
    const int* __restrict__ label,   // int32: JAX demotes int64 without x64 mode
    int C)
{
    const int row = blockIdx.x;
    const size_t base = (size_t)row * (size_t)C;
    const float4* __restrict__ x4 = reinterpret_cast<const float4*>(x + base);
    const int n4 = C >> 2;          // C assumed multiple of 4 (100000 is)

    float s = 0.0f;
    for (int i = threadIdx.x; i < n4; i += blockDim.x) {
        float4 v = x4[i];
        s += __expf(S_SCALE * v.x);
        s += __expf(S_SCALE * v.y);
        s += __expf(S_SCALE * v.z);
        s += __expf(S_SCALE * v.w);
    }
    // tail (C % 4) — not taken for C=100000 but keep it correct
    for (int i = (n4 << 2) + threadIdx.x; i < C; i += blockDim.x) {
        s += __expf(S_SCALE * x[base + i]);
    }

    // block reduction: warp shuffle then cross-warp via shared
    __shared__ float red[16];
    #pragma unroll
    for (int o = 16; o > 0; o >>= 1)
        s += __shfl_down_sync(0xffffffffu, s, o);
    if ((threadIdx.x & 31) == 0) red[threadIdx.x >> 5] = s;
    __syncthreads();
    if (threadIdx.x < 32) {
        float v = (threadIdx.x < (blockDim.x >> 5)) ? red[threadIdx.x] : 0.0f;
        #pragma unroll
        for (int o = 8; o > 0; o >>= 1)
            v += __shfl_down_sync(0xffffffffu, v, o);
        if (threadIdx.x == 0) {
            int lbl = label[row];
            // defensive clamp: never read outside the row even if dtype surprises us
            lbl = (lbl < 0) ? 0 : ((lbl >= C) ? C - 1 : lbl);
            const float xy = x[base + (size_t)lbl];
            const float num = S_SCALE * (xy - MARGIN);
            const float sum_excl = v - __expf(S_SCALE * xy);
            const float denom = __expf(num) + sum_excl;
            g_rowL[row] = (num - logf(denom)) / S_SCALE;
        }
    }
}

// Single-block deterministic reduction: out = -mean(L)
__global__ __launch_bounds__(1024) void final_reduce_kernel(float* __restrict__ out, int B)
{
    __shared__ float red[32];
    float s = 0.0f;
    for (int i = threadIdx.x; i < B; i += blockDim.x)
        s += g_rowL[i];
    #pragma unroll
    for (int o = 16; o > 0; o >>= 1)
        s += __shfl_down_sync(0xffffffffu, s, o);
    if ((threadIdx.x & 31) == 0) red[threadIdx.x >> 5] = s;
    __syncthreads();
    if (threadIdx.x < 32) {
        float v = (threadIdx.x < (blockDim.x >> 5)) ? red[threadIdx.x] : 0.0f;
        #pragma unroll
        for (int o = 16; o > 0; o >>= 1)
            v += __shfl_down_sync(0xffffffffu, v, o);
        if (threadIdx.x == 0)
            out[0] = -v / (float)B;
    }
}

extern "C" void kernel_launch(void* const* d_in, const int* in_sizes, int n_in,
                              void* d_out, int out_size)
{
    const float* x     = (const float*)d_in[0];
    const int*   label = (const int*)d_in[1];
    float*       out   = (float*)d_out;

    const int B = in_sizes[1];            // number of labels = rows
    const int C = in_sizes[0] / B;        // columns

    row_loss_kernel<<<B, 512>>>(x, label, C);
    final_reduce_kernel<<<1, 1024>>>(out, B);
}

// round 5
// speedup vs baseline: 1.0320x; 1.0320x over previous
#include <cuda_runtime.h>
#include <cuda_bf16.h>

#ifndef S_SCALE
#define S_SCALE 64.0f
#endif
#ifndef MARGIN
#define MARGIN 0.35f
#endif

__device__ float        g_sum;     // zero at module load; reset by last CTA each launch
__device__ unsigned int g_count;   // self-resetting via atomicInc wrap

// One CTA per row: sum exp(S*x) over the row, compute the per-row loss term,
// and fold it into the global mean via atomics (last CTA writes the output).
__global__ __launch_bounds__(512) void row_loss_kernel(
    const float* __restrict__ x,
    const int* __restrict__ label,   // int32 (JAX demotes int64 without x64 mode)
    float* __restrict__ out,
    int C, int B)
{
    const int row = blockIdx.x;
    const size_t base = (size_t)row * (size_t)C;
    const float4* __restrict__ x4 = reinterpret_cast<const float4*>(x + base);
    const int n4 = C >> 2;               // 25000 for C=100000
    const int nthreads = blockDim.x;

    float s = 0.0f;

    // 4-deep unrolled main loop: 4 outstanding LDG.128 per thread for MLP.
    int i = threadIdx.x;
    const int stride = nthreads;
    const int n4_4 = n4 - 3 * stride;
    for (; i < n4_4; i += 4 * stride) {
        float4 a = __ldcs(&x4[i]);
        float4 b = __ldcs(&x4[i + stride]);
        float4 c = __ldcs(&x4[i + 2 * stride]);
        float4 d = __ldcs(&x4[i + 3 * stride]);
        s += __expf(S_SCALE * a.x) + __expf(S_SCALE * a.y)
           + __expf(S_SCALE * a.z) + __expf(S_SCALE * a.w);
        s += __expf(S_SCALE * b.x) + __expf(S_SCALE * b.y)
           + __expf(S_SCALE * b.z) + __expf(S_SCALE * b.w);
        s += __expf(S_SCALE * c.x) + __expf(S_SCALE * c.y)
           + __expf(S_SCALE * c.z) + __expf(S_SCALE * c.w);
        s += __expf(S_SCALE * d.x) + __expf(S_SCALE * d.y)
           + __expf(S_SCALE * d.z) + __expf(S_SCALE * d.w);
    }
    for (; i < n4; i += stride) {
        float4 a = __ldcs(&x4[i]);
        s += __expf(S_SCALE * a.x) + __expf(S_SCALE * a.y)
           + __expf(S_SCALE * a.z) + __expf(S_SCALE * a.w);
    }
    // scalar tail (C % 4) — not taken for C=100000 but keep it correct
    for (int j = (n4 << 2) + threadIdx.x; j < C; j += stride) {
        s += __expf(S_SCALE * x[base + j]);
    }

    // block reduction: warp shuffle then cross-warp via shared
    __shared__ float red[16];
    #pragma unroll
    for (int o = 16; o > 0; o >>= 1)
        s += __shfl_down_sync(0xffffffffu, s, o);
    if ((threadIdx.x & 31) == 0) red[threadIdx.x >> 5] = s;
    __syncthreads();
    if (threadIdx.x < 32) {
        float v = (threadIdx.x < (nthreads >> 5)) ? red[threadIdx.x] : 0.0f;
        #pragma unroll
        for (int o = 8; o > 0; o >>= 1)
            v += __shfl_down_sync(0xffffffffu, v, o);
        if (threadIdx.x == 0) {
            int lbl = label[row];
            lbl = (lbl < 0) ? 0 : ((lbl >= C) ? C - 1 : lbl);   // defensive clamp
            const float xy = x[base + (size_t)lbl];
            const float num = S_SCALE * (xy - MARGIN);
            const float sum_excl = v - __expf(S_SCALE * xy);
            const float denom = __expf(num) + sum_excl;
            const float L = (num - logf(denom)) / S_SCALE;

            // fold into global mean; last CTA publishes and resets
            atomicAdd(&g_sum, L);
            __threadfence();
            unsigned t = atomicInc(&g_count, gridDim.x - 1); // wraps to 0 at last
            if (t == gridDim.x - 1) {
                out[0] = -g_sum / (float)B;
                g_sum = 0.0f;      // ready for next graph replay
            }
        }
    }
}

extern "C" void kernel_launch(void* const* d_in, const int* in_sizes, int n_in,
                              void* d_out, int out_size)
{
    const float* x     = (const float*)d_in[0];
    const int*   label = (const int*)d_in[1];
    float*       out   = (float*)d_out;

    const int B = in_sizes[1];            // rows = number of labels
    const int C = in_sizes[0] / B;        // columns

    row_loss_kernel<<<B, 512>>>(x, label, out, C, B);
}